// round 16
// baseline (speedup 1.0000x reference)
#include <cuda_runtime.h>
#include <cuda_bf16.h>
#include <cstdint>
#include <math.h>

// Problem constants
#define B 256
#define T 96
#define F 368
#define H 368
#define G3 1104          // 3*H
#define NC 29
#define OUT_NMS_OFF   (B*T)
#define OUT_FINE_OFF  (B*T + B*T*2)

// gru persistent config (HMMA version)
#define NCB_R 46                 // j-blocks of 8 cols
#define GRID_REC (2 * NCB_R)     // 92
#define THR_REC 256

// ---------------- device scratch ----------------
__device__ float g_xprojT[(size_t)T * G3 * B];      // (t, g, b)  b contiguous
__device__ float g_temporalT[(size_t)T * H * B];    // (t, k, b)  b contiguous
__device__ __nv_bfloat16 g_hh[2][(size_t)B * H];    // h bf16 hi, [b][k], double buffered
__device__ __nv_bfloat16 g_hl[2][(size_t)B * H];    // h bf16 lo
__device__ float g_logits[(size_t)B * T * 32];
__device__ float g_scores[(size_t)B * T * 2];
__device__ unsigned g_arrive[2][64 * 32];
__device__ unsigned g_release[64];

// ---------------- misc helpers ----------------
__device__ __forceinline__ float fsigmoid(float x) {
    return 1.f / (1.f + __expf(-x));
}
__device__ __forceinline__ float ftanh(float x) {
    float ex = __expf(2.f * x);
    return 1.f - 2.f / (ex + 1.f);
}
__device__ __forceinline__ uint32_t smem_u32(const void* p) {
    uint32_t a;
    asm("{ .reg .u64 t; cvta.to.shared.u64 t, %1; cvt.u32.u64 %0, t; }" : "=r"(a) : "l"(p));
    return a;
}

// ---------------- mma.sync / ldmatrix helpers (proven in R15) ----------------
__device__ __forceinline__ void ldsm_x4(uint32_t& r0, uint32_t& r1, uint32_t& r2, uint32_t& r3,
                                        uint32_t addr) {
    asm volatile("ldmatrix.sync.aligned.m8n8.x4.shared.b16 {%0,%1,%2,%3}, [%4];"
                 : "=r"(r0), "=r"(r1), "=r"(r2), "=r"(r3) : "r"(addr));
}
__device__ __forceinline__ void ldsm_x2(uint32_t& r0, uint32_t& r1, uint32_t addr) {
    asm volatile("ldmatrix.sync.aligned.m8n8.x2.shared.b16 {%0,%1}, [%2];"
                 : "=r"(r0), "=r"(r1) : "r"(addr));
}
__device__ __forceinline__ void mma_bf16(float* c, const uint32_t* a, uint32_t b0, uint32_t b1) {
    asm volatile(
        "mma.sync.aligned.m16n8k16.row.col.f32.bf16.bf16.f32 "
        "{%0,%1,%2,%3}, {%4,%5,%6,%7}, {%8,%9}, {%0,%1,%2,%3};"
        : "+f"(c[0]), "+f"(c[1]), "+f"(c[2]), "+f"(c[3])
        : "r"(a[0]), "r"(a[1]), "r"(a[2]), "r"(a[3]), "r"(b0), "r"(b1));
}

// bf16 split: x = hi + lo
__device__ __forceinline__ void bsplit2(float a, float b, uint32_t& hi, uint32_t& lo) {
    __nv_bfloat16 ha = __float2bfloat16(a);
    __nv_bfloat16 hb = __float2bfloat16(b);
    float ra = a - __bfloat162float(ha);
    float rb = b - __bfloat162float(hb);
    __nv_bfloat162 hp = __halves2bfloat162(ha, hb);
    __nv_bfloat162 lp = __halves2bfloat162(__float2bfloat16(ra), __float2bfloat16(rb));
    hi = *reinterpret_cast<uint32_t*>(&hp);
    lo = *reinterpret_cast<uint32_t*>(&lp);
}

// ================= Kernel 1: xproj via mma.sync bf16-split (unchanged, R15) =================
#define XSA 144
#define OA_HI 0
#define OA_LO 18432
#define OB_HI 36864
#define OB_LO 43776
#define XMM_SMEM 50688

__global__ __launch_bounds__(256) void xproj_mma(const float* __restrict__ feat,
                                                 const float* __restrict__ Wi,
                                                 const float* __restrict__ bi) {
    extern __shared__ char dsm[];
    const uint32_t sb = smem_u32(dsm);
    const int tid = threadIdx.x;
    const int wid = tid >> 5;
    const int lane = tid & 31;
    const int t  = blockIdx.x >> 1;
    const int b0 = (blockIdx.x & 1) << 7;
    const int gbase = blockIdx.y * 48;

    const int m0 = (wid & 3) * 32;
    const int n0 = (wid >> 2) * 24;

    const uint32_t aOff = (uint32_t)(m0 + (lane & 15)) * XSA + (uint32_t)(lane >> 4) * 16;
    const uint32_t bOff01 = (uint32_t)(n0 + (((lane >> 3) >> 1) << 3) + (lane & 7)) * XSA
                          + (uint32_t)((lane >> 3) & 1) * 16;
    const uint32_t bOff2 = (uint32_t)(n0 + 16 + (lane & 7)) * XSA
                         + (uint32_t)((lane >> 3) & 1) * 16;

    float acc[2][3][4];
#pragma unroll
    for (int i = 0; i < 2; i++)
#pragma unroll
        for (int j = 0; j < 3; j++)
#pragma unroll
            for (int q = 0; q < 4; q++) acc[i][j][q] = 0.f;

    for (int ch = 0; ch < 6; ch++) {
        const int kc = ch * 64;
        for (int q = tid; q < 128 * 16; q += 256) {
            int row = q >> 4;
            int kq4 = (q & 15) << 2;
            float4 v = make_float4(0.f, 0.f, 0.f, 0.f);
            if (kc + kq4 < F)
                v = *(const float4*)(feat + ((size_t)(b0 + row) * T + t) * F + kc + kq4);
            uint2 h, l;
            bsplit2(v.x, v.y, h.x, l.x);
            bsplit2(v.z, v.w, h.y, l.y);
            uint32_t off = (uint32_t)row * XSA + (uint32_t)kq4 * 2;
            *(uint2*)(dsm + OA_HI + off) = h;
            *(uint2*)(dsm + OA_LO + off) = l;
        }
        for (int q = tid; q < 48 * 16; q += 256) {
            int row = q >> 4;
            int kq4 = (q & 15) << 2;
            float4 v = make_float4(0.f, 0.f, 0.f, 0.f);
            if (kc + kq4 < F)
                v = *(const float4*)(Wi + (size_t)(gbase + row) * F + kc + kq4);
            uint2 h, l;
            bsplit2(v.x, v.y, h.x, l.x);
            bsplit2(v.z, v.w, h.y, l.y);
            uint32_t off = (uint32_t)row * XSA + (uint32_t)kq4 * 2;
            *(uint2*)(dsm + OB_HI + off) = h;
            *(uint2*)(dsm + OB_LO + off) = l;
        }
        __syncthreads();

#pragma unroll
        for (int ks = 0; ks < 4; ks++) {
            const uint32_t kb = (uint32_t)ks * 32;
            uint32_t ah[2][4], al[2][4];
#pragma unroll
            for (int mt = 0; mt < 2; mt++) {
                uint32_t base = sb + aOff + (uint32_t)mt * (16 * XSA) + kb;
                ldsm_x4(ah[mt][0], ah[mt][1], ah[mt][2], ah[mt][3], base + OA_HI);
                ldsm_x4(al[mt][0], al[mt][1], al[mt][2], al[mt][3], base + OA_LO);
            }
            uint32_t bh[3][2], bl[3][2];
            {
                uint32_t base01 = sb + bOff01 + kb;
                ldsm_x4(bh[0][0], bh[0][1], bh[1][0], bh[1][1], base01 + OB_HI);
                ldsm_x4(bl[0][0], bl[0][1], bl[1][0], bl[1][1], base01 + OB_LO);
                uint32_t base2 = sb + bOff2 + kb;
                ldsm_x2(bh[2][0], bh[2][1], base2 + OB_HI);
                ldsm_x2(bl[2][0], bl[2][1], base2 + OB_LO);
            }
#pragma unroll
            for (int mt = 0; mt < 2; mt++)
#pragma unroll
                for (int nt = 0; nt < 3; nt++) {
                    mma_bf16(acc[mt][nt], ah[mt], bh[nt][0], bh[nt][1]);
                    mma_bf16(acc[mt][nt], ah[mt], bl[nt][0], bl[nt][1]);
                    mma_bf16(acc[mt][nt], al[mt], bh[nt][0], bh[nt][1]);
                }
        }
        __syncthreads();
    }

    float* sC = (float*)dsm;
    {
        const int r0 = lane >> 2;
        const int c0 = (lane & 3) * 2;
#pragma unroll
        for (int mt = 0; mt < 2; mt++)
#pragma unroll
            for (int nt = 0; nt < 3; nt++) {
                int m = m0 + mt * 16 + r0;
                int g = n0 + nt * 8 + c0;
                sC[(size_t)g * 132 + m]           = acc[mt][nt][0];
                sC[(size_t)(g + 1) * 132 + m]     = acc[mt][nt][1];
                sC[(size_t)g * 132 + m + 8]       = acc[mt][nt][2];
                sC[(size_t)(g + 1) * 132 + m + 8] = acc[mt][nt][3];
            }
    }
    __syncthreads();
    for (int q = tid; q < 48 * 128; q += 256) {
        int g = q >> 7;
        int b = q & 127;
        int gg = gbase + g;
        g_xprojT[((size_t)t * G3 + gg) * B + b0 + b] = sC[(size_t)g * 132 + b] + __ldg(bi + gg);
    }
}

// ---------------- barrier resets + dummy ----------------
__global__ void reset_arrive_kernel() {
    int tid = threadIdx.x;
    for (int q = tid; q < 2 * 64 * 32; q += 256) {
        ((unsigned*)g_arrive)[q] = 0u;
    }
}
__global__ void reset_release_kernel() {
    if (threadIdx.x < 64) g_release[threadIdx.x] = 0u;
}
__global__ void noop_kernel() {}

// ---------------- per-half grid barrier (46 blocks/half) ----------------
__device__ __forceinline__ void half_barrier(int bh, int cb, unsigned s) {
    __syncthreads();
    if (threadIdx.x == 0) {
        __threadfence();
        *(volatile unsigned*)&g_arrive[bh][cb * 32] = s;
    }
    if (cb == 0 && threadIdx.x < 23) {
        int i0 = threadIdx.x * 2;
        int i1 = i0 + 1;
        bool done = false;
        while (!done) {
            unsigned a = *(volatile unsigned*)&g_arrive[bh][i0 * 32];
            unsigned c = (i1 < NCB_R) ? *(volatile unsigned*)&g_arrive[bh][i1 * 32] : s;
            done = __all_sync(0x007fffffu, (a >= s) && (c >= s));
        }
        if (threadIdx.x == 0) {
            __threadfence();
            *(volatile unsigned*)&g_release[bh * 32] = s;
        }
    }
    if (threadIdx.x == 0) {
        while (*(volatile unsigned*)&g_release[bh * 32] < s) { }
        __threadfence();
    }
    __syncthreads();
}

// ================= persistent GRU recurrence via HMMA =================
// Block = (b-half: M=128) x (8 j-cols: N=24 = 3 gates x 8 j). K=368, 2 chunks (192+176).
// Warp wid owns m-tile m0 = wid*16; all warps share the 24-row B (Wh slice, bf16-split, SMEM-resident).
#define RASTRIDE 400             // A row stride bytes (192 bf16 max + pad), bank-shift 4
#define RBSTRIDE 752             // B row stride bytes (368 bf16 + pad), bank-shift 28
#define OBH 0
#define OBL 18048                // 24*752
#define OAH 36096
#define OAL (36096 + 51200)      // 128*400
#define GRU_SMEM (36096 + 102400)  // 138496

__global__ __launch_bounds__(THR_REC, 1) void gru_persistent(const float* __restrict__ Wh,
                                                             const float* __restrict__ bhb) {
    extern __shared__ char dsm[];
    const uint32_t sb = smem_u32(dsm);
    const int tid = threadIdx.x;
    const int wid = tid >> 5;
    const int lane = tid & 31;
    const int bh = blockIdx.x & 1;
    const int cb = blockIdx.x >> 1;          // 0..45
    const int j0 = cb * 8;
    const int m0 = wid * 16;
    const int bhbase = bh * 128;

    // ---- pre-split Wh slice into SMEM (rows n: gate=n>>3, j=j0+(n&7)) ----
    for (int q = tid; q < 24 * 92; q += THR_REC) {
        int row = q / 92;
        int kq4 = (q % 92) * 4;
        int g = row >> 3;
        int j = j0 + (row & 7);
        float4 v = *(const float4*)(Wh + ((size_t)g * H + j) * H + kq4);
        uint2 h, l;
        bsplit2(v.x, v.y, h.x, l.x);
        bsplit2(v.z, v.w, h.y, l.y);
        uint32_t off = (uint32_t)row * RBSTRIDE + (uint32_t)kq4 * 2;
        *(uint2*)(dsm + OBH + off) = h;
        *(uint2*)(dsm + OBL + off) = l;
    }

    // fragment address offsets (cloned from proven xproj patterns; n0 = 0)
    const uint32_t aOff = (uint32_t)(m0 + (lane & 15)) * RASTRIDE + (uint32_t)(lane >> 4) * 16;
    const uint32_t bOff01 = (uint32_t)((((lane >> 3) >> 1) << 3) + (lane & 7)) * RBSTRIDE
                          + (uint32_t)((lane >> 3) & 1) * 16;
    const uint32_t bOff2 = (uint32_t)(16 + (lane & 7)) * RBSTRIDE
                         + (uint32_t)((lane >> 3) & 1) * 16;

    // gate role: thread holds (b, j) pairs q=0..3:
    //   b_q = bhbase + m0 + (lane>>2) + (q>=2 ? 8 : 0),  j_q = j0 + (lane&3)*2 + (q&1)
    const int r0 = lane >> 2;
    const int c0 = (lane & 3) * 2;
    float gbias[3][2];
#pragma unroll
    for (int g = 0; g < 3; g++)
#pragma unroll
        for (int jq = 0; jq < 2; jq++)
            gbias[g][jq] = bhb[g * H + j0 + c0 + jq];
    __syncthreads();

    for (int t = 0; t < T; t++) {
        const int par = t & 1;
        const int prev = par ^ 1;

        // ---- prefetch gi + hp ----
        float gi[3][4], hp[4];
#pragma unroll
        for (int q = 0; q < 4; q++) {
            int b = bhbase + m0 + r0 + ((q >> 1) << 3);
            int j = j0 + c0 + (q & 1);
#pragma unroll
            for (int g = 0; g < 3; g++)
                gi[g][q] = g_xprojT[((size_t)t * G3 + g * H + j) * B + b];
            hp[q] = (t > 0) ? g_temporalT[((size_t)(t - 1) * H + j) * B + b] : 0.f;
        }

        float acc[3][4];
#pragma unroll
        for (int nt = 0; nt < 3; nt++)
#pragma unroll
            for (int q = 0; q < 4; q++) acc[nt][q] = 0.f;

        if (t > 0) {
            const __nv_bfloat16* hhp = g_hh[prev];
            const __nv_bfloat16* hlp = g_hl[prev];
#pragma unroll
            for (int ch = 0; ch < 2; ch++) {
                const int kc = ch ? 192 : 0;
                const int nk4 = ch ? 44 : 48;
                const int nk = ch ? 11 : 12;
                // load A chunk: 128 rows x nk4*4 bf16 (hi/lo) from global bf16 h
                for (int q = tid; q < 128 * nk4; q += THR_REC) {
                    int row = q / nk4;
                    int k4 = (q % nk4) * 4;
                    size_t gidx = (size_t)(bhbase + row) * H + kc + k4;
                    uint32_t off = (uint32_t)row * RASTRIDE + (uint32_t)k4 * 2;
                    *(uint2*)(dsm + OAH + off) = *(const uint2*)(hhp + gidx);
                    *(uint2*)(dsm + OAL + off) = *(const uint2*)(hlp + gidx);
                }
                __syncthreads();

                for (int ks = 0; ks < nk; ks++) {
                    const uint32_t kb = (uint32_t)ks * 32;
                    uint32_t ah[4], al[4];
                    {
                        uint32_t base = sb + aOff + kb;
                        ldsm_x4(ah[0], ah[1], ah[2], ah[3], base + OAH);
                        ldsm_x4(al[0], al[1], al[2], al[3], base + OAL);
                    }
                    uint32_t bhf[3][2], blf[3][2];
                    {
                        uint32_t kpos = (uint32_t)kc * 2 + kb;
                        uint32_t base01 = sb + bOff01 + kpos;
                        ldsm_x4(bhf[0][0], bhf[0][1], bhf[1][0], bhf[1][1], base01 + OBH);
                        ldsm_x4(blf[0][0], blf[0][1], blf[1][0], blf[1][1], base01 + OBL);
                        uint32_t base2 = sb + bOff2 + kpos;
                        ldsm_x2(bhf[2][0], bhf[2][1], base2 + OBH);
                        ldsm_x2(blf[2][0], blf[2][1], base2 + OBL);
                    }
#pragma unroll
                    for (int nt = 0; nt < 3; nt++) {
                        mma_bf16(acc[nt], ah, bhf[nt][0], bhf[nt][1]);   // hi*hi
                        mma_bf16(acc[nt], ah, blf[nt][0], blf[nt][1]);   // hi*lo
                        mma_bf16(acc[nt], al, bhf[nt][0], bhf[nt][1]);   // lo*hi
                    }
                }
                __syncthreads();
            }
        }

        // ---- gates: fully register-local (nt 0=r, 1=z, 2=n) ----
        __nv_bfloat16* hhw = g_hh[par];
        __nv_bfloat16* hlw = g_hl[par];
#pragma unroll
        for (int q = 0; q < 4; q++) {
            int b = bhbase + m0 + r0 + ((q >> 1) << 3);
            int j = j0 + c0 + (q & 1);
            int jq = q & 1;
            float r = fsigmoid(gi[0][q] + acc[0][q] + gbias[0][jq]);
            float z = fsigmoid(gi[1][q] + acc[1][q] + gbias[1][jq]);
            float n = ftanh(gi[2][q] + r * (acc[2][q] + gbias[2][jq]));
            float h = (1.f - z) * n + z * hp[q];
            g_temporalT[((size_t)t * H + j) * B + b] = h;
            __nv_bfloat16 hb16 = __float2bfloat16(h);
            float lo = h - __bfloat162float(hb16);
            size_t hidx = (size_t)b * H + j;
            hhw[hidx] = hb16;
            hlw[hidx] = __float2bfloat16(lo);
        }

        if (t < T - 1) half_barrier(bh, cb, (unsigned)(t + 1));
    }
}

// ---------------- Kernel 3a: heads GEMM -> logits ----------------
#define BK 16
__global__ __launch_bounds__(256) void heads_gemm(const float* __restrict__ Wc,
                                                  const float* __restrict__ bc,
                                                  const float* __restrict__ Wf,
                                                  const float* __restrict__ bf) {
    __shared__ float As[BK][128];
    __shared__ float Ws[BK][32];
    const int t  = blockIdx.x >> 1;
    const int b0 = (blockIdx.x & 1) * 128;
    const int tid = threadIdx.x;
    const int tx = tid % 8;
    const int ty = tid / 8;

    float acc[4][4];
#pragma unroll
    for (int i = 0; i < 4; i++)
#pragma unroll
        for (int j = 0; j < 4; j++) acc[i][j] = 0.f;

    const float* hT = g_temporalT + (size_t)t * H * B;

    for (int kt = 0; kt < H; kt += BK) {
#pragma unroll
        for (int l = 0; l < 2; l++) {
            int idx = tid + l * 256;
            int krow = idx >> 5;
            int bq = idx & 31;
            *(float4*)&As[krow][bq * 4] =
                *(const float4*)(hT + (size_t)(kt + krow) * B + b0 + bq * 4);
        }
        if (tid < 128) {
            int n = tid >> 2;
            int kq = tid & 3;
            float4 v = make_float4(0.f, 0.f, 0.f, 0.f);
            if (n < 2)       v = *(const float4*)(Wc + (size_t)n * H + kt + kq * 4);
            else if (n < 31) v = *(const float4*)(Wf + (size_t)(n - 2) * H + kt + kq * 4);
            Ws[kq * 4 + 0][n] = v.x;
            Ws[kq * 4 + 1][n] = v.y;
            Ws[kq * 4 + 2][n] = v.z;
            Ws[kq * 4 + 3][n] = v.w;
        }
        __syncthreads();
#pragma unroll
        for (int k = 0; k < BK; k++) {
            float a[4], w[4];
            *(float4*)a = *(const float4*)&As[k][ty * 4];
            *(float4*)w = *(const float4*)&Ws[k][tx * 4];
#pragma unroll
            for (int i = 0; i < 4; i++)
#pragma unroll
                for (int j = 0; j < 4; j++)
                    acc[i][j] = fmaf(a[i], w[j], acc[i][j]);
        }
        __syncthreads();
    }

#pragma unroll
    for (int i = 0; i < 4; i++) {
        int b = b0 + ty * 4 + i;
        float4 v;
        float* vp = (float*)&v;
#pragma unroll
        for (int j = 0; j < 4; j++) {
            int n = tx * 4 + j;
            float bias = (n < 2) ? bc[n] : ((n < 31) ? bf[n - 2] : 0.f);
            vp[j] = acc[i][j] + bias;
        }
        *(float4*)&g_logits[((size_t)t * B + b) * 32 + tx * 4] = v;
    }
}

// ---------------- Kernel 3b: activations ----------------
__global__ __launch_bounds__(256) void act_kernel(float* __restrict__ out) {
    int idx = blockIdx.x * blockDim.x + threadIdx.x;
    if (idx >= B * T) return;
    int t = idx >> 8;
    int b = idx & 255;
    const float* lg = g_logits + (size_t)idx * 32;
    float logit[32];
#pragma unroll
    for (int q = 0; q < 8; q++)
        *(float4*)&logit[q * 4] = *(const float4*)&lg[q * 4];

    float l0 = logit[0], l1 = logit[1];
    float m = fmaxf(l0, l1);
    float e0 = __expf(l0 - m), e1 = __expf(l1 - m);
    float inv = 1.f / (e0 + e1);
    size_t oidx = (size_t)b * T + t;
    g_scores[oidx * 2 + 0] = e0 * inv;
    g_scores[oidx * 2 + 1] = e1 * inv;

    float* fine = out + OUT_FINE_OFF + oidx * NC;
#pragma unroll
    for (int i = 0; i < NC; i++) fine[i] = fsigmoid(logit[2 + i]);
}

// ---------------- Kernel 4: NMS + decisions ----------------
__global__ void nms_kernel(float* __restrict__ out) {
    int idx = blockIdx.x * blockDim.x + threadIdx.x;
    if (idx >= B * T) return;
    int b = idx / T;
    int t = idx % T;
    const float* sb = g_scores + (size_t)b * T * 2;
    float s0 = sb[t * 2 + 0];
    float s1 = sb[t * 2 + 1];
    float wmin = INFINITY;
#pragma unroll
    for (int k = -2; k <= 2; k++) {
        int tt = t + k;
        if (tt >= 0 && tt < T) wmin = fminf(wmin, sb[tt * 2]);
    }
    bool keep = (s0 == wmin);
    float o0 = keep ? s0 : 0.f;
    float o1 = keep ? s1 : 0.f;
    out[idx] = (o1 > o0) ? 1.0f : 0.0f;
    out[OUT_NMS_OFF + (size_t)idx * 2 + 0] = o0;
    out[OUT_NMS_OFF + (size_t)idx * 2 + 1] = o1;
}

// ---------------- launch ----------------
extern "C" void kernel_launch(void* const* d_in, const int* in_sizes, int n_in,
                              void* d_out, int out_size) {
    const float* feat = (const float*)d_in[0];
    const float* Wi  = (const float*)d_in[2];
    const float* Wh  = (const float*)d_in[3];
    const float* bi  = (const float*)d_in[4];
    const float* bhb = (const float*)d_in[5];
    const float* Wc  = (const float*)d_in[6];
    const float* bc  = (const float*)d_in[7];
    const float* Wf  = (const float*)d_in[8];
    const float* bf  = (const float*)d_in[9];
    float* out = (float*)d_out;

    cudaFuncSetAttribute(xproj_mma, cudaFuncAttributeMaxDynamicSharedMemorySize, XMM_SMEM);
    cudaFuncSetAttribute(gru_persistent, cudaFuncAttributeMaxDynamicSharedMemorySize, GRU_SMEM);

    // order: gru_persistent lands in the ncu-profiled slot (4th launch)
    reset_arrive_kernel<<<1, 256>>>();                          // 1
    reset_release_kernel<<<1, 64>>>();                          // 2
    dim3 g1(T * 2, G3 / 48);                                    // 192 x 23
    xproj_mma<<<g1, 256, XMM_SMEM>>>(feat, Wi, bi);             // 3
    gru_persistent<<<GRID_REC, THR_REC, GRU_SMEM>>>(Wh, bhb);   // 4 <- profiled
    heads_gemm<<<T * 2, 256>>>(Wc, bc, Wf, bf);                 // 5
    act_kernel<<<(B * T + 255) / 256, 256>>>(out);              // 6
    nms_kernel<<<(B * T + 255) / 256, 256>>>(out);              // 7
}

// round 17
// speedup vs baseline: 1.8413x; 1.8413x over previous
#include <cuda_runtime.h>
#include <cuda_bf16.h>
#include <cstdint>
#include <math.h>

// Problem constants
#define B 256
#define T 96
#define F 368
#define H 368
#define G3 1104          // 3*H
#define NC 29
#define OUT_NMS_OFF   (B*T)
#define OUT_FINE_OFF  (B*T + B*T*2)

// gru persistent config (R12, proven)
#define NCB 62
#define GRU_GRID 124
#define GRU_THR 512

// ---------------- device scratch ----------------
__device__ float g_xprojT[(size_t)T * G3 * B];      // (t, g, b)  b contiguous
__device__ float g_temporalT[(size_t)T * H * B];    // (t, k, b)  b contiguous
__device__ __nv_bfloat16 g_fh[(size_t)B * T * F];   // feat bf16 hi (same layout as feat)
__device__ __nv_bfloat16 g_fl[(size_t)B * T * F];   // feat bf16 lo
__device__ __nv_bfloat16 g_wh[(size_t)G3 * F];      // Wi bf16 hi
__device__ __nv_bfloat16 g_wl[(size_t)G3 * F];      // Wi bf16 lo
__device__ float g_logits[(size_t)B * T * 32];
__device__ float g_scores[(size_t)B * T * 2];
__device__ unsigned g_arrive[2][NCB * 32];
__device__ unsigned g_release[64];

// ---------------- f32x2 packed helpers (gru) ----------------
__device__ __forceinline__ unsigned long long fma2(unsigned long long a,
                                                   unsigned long long b,
                                                   unsigned long long c) {
    unsigned long long d;
    asm("fma.rn.f32x2 %0, %1, %2, %3;" : "=l"(d) : "l"(a), "l"(b), "l"(c));
    return d;
}
__device__ __forceinline__ unsigned long long add2(unsigned long long a,
                                                   unsigned long long b) {
    unsigned long long d;
    asm("add.rn.f32x2 %0, %1, %2;" : "=l"(d) : "l"(a), "l"(b));
    return d;
}
__device__ __forceinline__ unsigned long long packdup(float x) {
    unsigned long long r;
    unsigned u = __float_as_uint(x);
    asm("mov.b64 %0, {%1, %1};" : "=l"(r) : "r"(u));
    return r;
}
__device__ __forceinline__ float lo32(unsigned long long v) {
    return __uint_as_float((unsigned)v);
}
__device__ __forceinline__ float hi32(unsigned long long v) {
    return __uint_as_float((unsigned)(v >> 32));
}
__device__ __forceinline__ float fsigmoid(float x) {
    return 1.f / (1.f + __expf(-x));
}
__device__ __forceinline__ float ftanh(float x) {
    float ex = __expf(2.f * x);
    return 1.f - 2.f / (ex + 1.f);
}
__device__ __forceinline__ uint32_t smem_u32(const void* p) {
    uint32_t a;
    asm("{ .reg .u64 t; cvta.to.shared.u64 t, %1; cvt.u32.u64 %0, t; }" : "=r"(a) : "l"(p));
    return a;
}

// ---------------- mma.sync / ldmatrix helpers (proven R15) ----------------
__device__ __forceinline__ void ldsm_x4(uint32_t& r0, uint32_t& r1, uint32_t& r2, uint32_t& r3,
                                        uint32_t addr) {
    asm volatile("ldmatrix.sync.aligned.m8n8.x4.shared.b16 {%0,%1,%2,%3}, [%4];"
                 : "=r"(r0), "=r"(r1), "=r"(r2), "=r"(r3) : "r"(addr));
}
__device__ __forceinline__ void mma_bf16(float* c, const uint32_t* a, uint32_t b0, uint32_t b1) {
    asm volatile(
        "mma.sync.aligned.m16n8k16.row.col.f32.bf16.bf16.f32 "
        "{%0,%1,%2,%3}, {%4,%5,%6,%7}, {%8,%9}, {%0,%1,%2,%3};"
        : "+f"(c[0]), "+f"(c[1]), "+f"(c[2]), "+f"(c[3])
        : "r"(a[0]), "r"(a[1]), "r"(a[2]), "r"(a[3]), "r"(b0), "r"(b1));
}

// bf16 split: x = hi + lo
__device__ __forceinline__ void bsplit2(float a, float b, uint32_t& hi, uint32_t& lo) {
    __nv_bfloat16 ha = __float2bfloat16(a);
    __nv_bfloat16 hb = __float2bfloat16(b);
    float ra = a - __bfloat162float(ha);
    float rb = b - __bfloat162float(hb);
    __nv_bfloat162 hp = __halves2bfloat162(ha, hb);
    __nv_bfloat162 lp = __halves2bfloat162(__float2bfloat16(ra), __float2bfloat16(rb));
    hi = *reinterpret_cast<uint32_t*>(&hp);
    lo = *reinterpret_cast<uint32_t*>(&lp);
}

// ================= Kernel 0: pre-split feat + Wi into bf16 hi/lo =================
__global__ __launch_bounds__(256) void split_kernel(const float* __restrict__ feat,
                                                    const float* __restrict__ Wi) {
    const int n1 = (B * T * F) / 4;       // feat float4 count
    const int n2 = (G3 * F) / 4;          // Wi float4 count
    for (int idx = blockIdx.x * blockDim.x + threadIdx.x; idx < n1 + n2;
         idx += gridDim.x * blockDim.x) {
        const float* src;
        __nv_bfloat16 *dh, *dl;
        if (idx < n1) {
            src = feat + (size_t)idx * 4;
            dh = g_fh + (size_t)idx * 4;
            dl = g_fl + (size_t)idx * 4;
        } else {
            int j = idx - n1;
            src = Wi + (size_t)j * 4;
            dh = g_wh + (size_t)j * 4;
            dl = g_wl + (size_t)j * 4;
        }
        float4 v = *(const float4*)src;
        uint2 h, l;
        bsplit2(v.x, v.y, h.x, l.x);
        bsplit2(v.z, v.w, h.y, l.y);
        *(uint2*)dh = h;
        *(uint2*)dl = l;
    }
}

// ================= Kernel 1: xproj via mma.sync (t-paired, N=96) =================
// block: (t-pair, b-half) x 96-g slice (G3 padded 1104->1152, guarded).
// M=128 per t (2 t share the B tile), K=368 in 6 chunks of 64.
#define XSA 144               // SMEM row stride bytes
#define OA_HI 0               // A: 256 rows (t0:0-127, t1:128-255) -> 36864 B
#define OA_LO 36864
#define OB_HI 73728           // B: 96 rows -> 13824 B
#define OB_LO 87552
#define XMM_SMEM 101376

__global__ __launch_bounds__(256) void xproj_mma(const float* __restrict__ bi) {
    extern __shared__ char dsm[];
    const uint32_t sb = smem_u32(dsm);
    const int tid = threadIdx.x;
    const int wid = tid >> 5;
    const int lane = tid & 31;
    const int tp = blockIdx.x >> 1;          // t-pair 0..47
    const int b0 = (blockIdx.x & 1) << 7;
    const int t0 = tp * 2;
    const int gbase = blockIdx.y * 96;

    const int m0 = (wid & 3) * 32;           // 2 m-tiles of 16
    const int n0 = (wid >> 2) * 48;          // 6 n-tiles of 8

    // ldmatrix lane offsets (proven R15 patterns)
    const uint32_t aOff = (uint32_t)(m0 + (lane & 15)) * XSA + (uint32_t)(lane >> 4) * 16;
    const uint32_t bOff01 = (uint32_t)(n0 + (((lane >> 3) >> 1) << 3) + (lane & 7)) * XSA
                          + (uint32_t)((lane >> 3) & 1) * 16;

    float acc[2][2][6][4];
#pragma unroll
    for (int tt = 0; tt < 2; tt++)
#pragma unroll
        for (int mt = 0; mt < 2; mt++)
#pragma unroll
            for (int nt = 0; nt < 6; nt++)
#pragma unroll
                for (int q = 0; q < 4; q++) acc[tt][mt][nt][q] = 0.f;

    for (int ch = 0; ch < 6; ch++) {
        const int kc = ch * 64;
        // ---- A: 256 rows (2 t) x 64 k, 8 uint4 per row ----
        for (int q = tid; q < 256 * 8; q += 256) {
            int row = q >> 3;
            int k8  = (q & 7) << 3;
            int kab = kc + k8;
            int tt = t0 + (row >> 7);
            int r = row & 127;
            uint4 vh = make_uint4(0u, 0u, 0u, 0u);
            uint4 vl = vh;
            if (kab < F) {
                size_t gidx = ((size_t)(b0 + r) * T + tt) * F + kab;
                vh = *(const uint4*)(g_fh + gidx);
                vl = *(const uint4*)(g_fl + gidx);
            }
            uint32_t off = (uint32_t)row * XSA + (uint32_t)k8 * 2;
            *(uint4*)(dsm + OA_HI + off) = vh;
            *(uint4*)(dsm + OA_LO + off) = vl;
        }
        // ---- B: 96 rows x 64 k ----
        for (int q = tid; q < 96 * 8; q += 256) {
            int row = q >> 3;
            int k8  = (q & 7) << 3;
            int kab = kc + k8;
            int gg = gbase + row;
            uint4 vh = make_uint4(0u, 0u, 0u, 0u);
            uint4 vl = vh;
            if (kab < F && gg < G3) {
                size_t gidx = (size_t)gg * F + kab;
                vh = *(const uint4*)(g_wh + gidx);
                vl = *(const uint4*)(g_wl + gidx);
            }
            uint32_t off = (uint32_t)row * XSA + (uint32_t)k8 * 2;
            *(uint4*)(dsm + OB_HI + off) = vh;
            *(uint4*)(dsm + OB_LO + off) = vl;
        }
        __syncthreads();

#pragma unroll
        for (int ks = 0; ks < 4; ks++) {
            const uint32_t kb = (uint32_t)ks * 32;
            uint32_t ah[2][2][4], al[2][2][4];
#pragma unroll
            for (int tt = 0; tt < 2; tt++)
#pragma unroll
                for (int mt = 0; mt < 2; mt++) {
                    uint32_t base = sb + aOff + (uint32_t)(tt * 128 + mt * 16) * XSA + kb;
                    ldsm_x4(ah[tt][mt][0], ah[tt][mt][1], ah[tt][mt][2], ah[tt][mt][3],
                            base + OA_HI);
                    ldsm_x4(al[tt][mt][0], al[tt][mt][1], al[tt][mt][2], al[tt][mt][3],
                            base + OA_LO);
                }
            uint32_t bh[6][2], bl[6][2];
#pragma unroll
            for (int p = 0; p < 3; p++) {
                uint32_t base01 = sb + bOff01 + (uint32_t)(p * 16) * XSA + kb;
                ldsm_x4(bh[2 * p][0], bh[2 * p][1], bh[2 * p + 1][0], bh[2 * p + 1][1],
                        base01 + OB_HI);
                ldsm_x4(bl[2 * p][0], bl[2 * p][1], bl[2 * p + 1][0], bl[2 * p + 1][1],
                        base01 + OB_LO);
            }
#pragma unroll
            for (int tt = 0; tt < 2; tt++)
#pragma unroll
                for (int mt = 0; mt < 2; mt++)
#pragma unroll
                    for (int nt = 0; nt < 6; nt++) {
                        mma_bf16(acc[tt][mt][nt], ah[tt][mt], bh[nt][0], bh[nt][1]); // hi*hi
                        mma_bf16(acc[tt][mt][nt], ah[tt][mt], bl[nt][0], bl[nt][1]); // hi*lo
                        mma_bf16(acc[tt][mt][nt], al[tt][mt], bh[nt][0], bh[nt][1]); // lo*hi
                    }
        }
        __syncthreads();
    }

    // ---- epilogue per t: transpose via SMEM [96 g][132 b], coalesced store ----
    float* sC = (float*)dsm;
    const int r0 = lane >> 2;
    const int c0 = (lane & 3) * 2;
#pragma unroll
    for (int tt = 0; tt < 2; tt++) {
#pragma unroll
        for (int mt = 0; mt < 2; mt++)
#pragma unroll
            for (int nt = 0; nt < 6; nt++) {
                int m = m0 + mt * 16 + r0;
                int g = n0 + nt * 8 + c0;
                sC[(size_t)g * 132 + m]           = acc[tt][mt][nt][0];
                sC[(size_t)(g + 1) * 132 + m]     = acc[tt][mt][nt][1];
                sC[(size_t)g * 132 + m + 8]       = acc[tt][mt][nt][2];
                sC[(size_t)(g + 1) * 132 + m + 8] = acc[tt][mt][nt][3];
            }
        __syncthreads();
        int tcur = t0 + tt;
        for (int q = tid; q < 96 * 128; q += 256) {
            int g = q >> 7;
            int b = q & 127;
            int gg = gbase + g;
            if (gg < G3)
                g_xprojT[((size_t)tcur * G3 + gg) * B + b0 + b] =
                    sC[(size_t)g * 132 + b] + __ldg(bi + gg);
        }
        __syncthreads();
    }
}

// ---------------- barrier resets ----------------
__global__ void reset_arrive_kernel() {
    int tid = threadIdx.x;
    for (int q = tid; q < 2 * NCB * 32; q += 256) {
        ((unsigned*)g_arrive)[q] = 0u;
    }
}
__global__ void reset_release_kernel() {
    if (threadIdx.x < 64) g_release[threadIdx.x] = 0u;
}

// ---------------- per-half grid barrier (R12) ----------------
__device__ __forceinline__ void half_barrier(int bh, int cb, unsigned s) {
    __syncthreads();
    if (threadIdx.x == 0) {
        __threadfence();
        *(volatile unsigned*)&g_arrive[bh][cb * 32] = s;
    }
    if (cb == 0 && threadIdx.x < 31) {
        int i0 = threadIdx.x * 2;
        int i1 = i0 + 1;
        bool done = false;
        while (!done) {
            unsigned a = *(volatile unsigned*)&g_arrive[bh][i0 * 32];
            unsigned c = (i1 < NCB) ? *(volatile unsigned*)&g_arrive[bh][i1 * 32] : s;
            done = __all_sync(0x7fffffffu, (a >= s) && (c >= s));
        }
        if (threadIdx.x == 0) {
            __threadfence();
            *(volatile unsigned*)&g_release[bh * 32] = s;
        }
    }
    if (threadIdx.x == 0) {
        while (*(volatile unsigned*)&g_release[bh * 32] < s) { }
        __threadfence();
    }
    __syncthreads();
}

// ---------------- persistent GRU recurrence (R12, proven fp32 f32x2) ----------------
#define RED(r, c, kg, lane) red[((((r) * 2 + (c)) * 4 + (kg)) << 6) + (lane)]

__global__ __launch_bounds__(GRU_THR, 1) void gru_persistent(const float* __restrict__ Wh,
                                                             const float* __restrict__ bhb) {
    __shared__ float wsp[9 * H * 2];
    __shared__ unsigned long long red[9 * 2 * 4 * 64];
    const int tid = threadIdx.x;
    const int bh = blockIdx.x & 1;
    const int cb = blockIdx.x >> 1;
    const int j0 = cb * 6;
    const int kg   = tid >> 6;
    const int lane = tid & 63;
    const int k0 = kg * 46;
    const int bP = bh * 128 + 2 * lane;

    const int gp  = tid >> 7;
    const int gb2 = tid & 127;
    const int gc   = gb2 & 1;
    const int glan = gb2 >> 1;
    const int gbb = bh * 128 + gb2;
    const int gja = j0 + 2 * gp;
    const bool gate = (tid < 384) && (gja < H);

    for (int q = tid; q < 9 * H; q += GRU_THR) {
        int row = q / H;
        int k   = q % H;
        int p = row / 3, g = row % 3;
        int ja = j0 + 2 * p, jb = ja + 1;
        float lo = (ja < H) ? Wh[((size_t)g * H + ja) * H + k] : 0.f;
        float hi = (jb < H) ? Wh[((size_t)g * H + jb) * H + k] : 0.f;
        wsp[(size_t)q * 2 + 0] = lo;
        wsp[(size_t)q * 2 + 1] = hi;
    }
    float gbias[2][3];
    if (gate) {
#pragma unroll
        for (int c = 0; c < 2; c++)
#pragma unroll
            for (int g = 0; g < 3; g++)
                gbias[c][g] = bhb[g * H + gja + c];
    }
    __syncthreads();

    for (int t = 0; t < T; t++) {
        const float* hprevT = g_temporalT + (size_t)(t - 1) * H * B;

        float gi[2][3];
        float hp[2];
        if (gate) {
            const float* xp = g_xprojT + (size_t)t * G3 * B + gbb;
#pragma unroll
            for (int c = 0; c < 2; c++) {
                int j = gja + c;
                gi[c][0] = xp[(size_t)(0 * H + j) * B];
                gi[c][1] = xp[(size_t)(1 * H + j) * B];
                gi[c][2] = xp[(size_t)(2 * H + j) * B];
                hp[c] = (t > 0) ? hprevT[(size_t)j * B + gbb] : 0.f;
            }
        }

        unsigned long long acc[9][2];
#pragma unroll
        for (int r = 0; r < 9; r++) { acc[r][0] = 0ull; acc[r][1] = 0ull; }

        if (t > 0) {
            const float* hbase = hprevT + (size_t)k0 * B + bP;
            float2 h0 = *(const float2*)(hbase);
            float2 h1 = *(const float2*)(hbase + B);
#pragma unroll 2
            for (int k2 = 0; k2 < 23; k2++) {
                float2 n0v, n1v;
                if (k2 < 22) {
                    n0v = *(const float2*)(hbase + (size_t)(2 * k2 + 2) * B);
                    n1v = *(const float2*)(hbase + (size_t)(2 * k2 + 3) * B);
                }
                unsigned long long a0 = packdup(h0.x);
                unsigned long long a1 = packdup(h0.y);
                unsigned long long c0 = packdup(h1.x);
                unsigned long long c1 = packdup(h1.y);
                const float* wk = wsp + (size_t)(k0 + 2 * k2) * 2;
#pragma unroll
                for (int r = 0; r < 9; r++) {
                    ulonglong2 w = *(const ulonglong2*)(wk + (size_t)r * (H * 2));
                    acc[r][0] = fma2(a0, w.x, acc[r][0]);
                    acc[r][1] = fma2(a1, w.x, acc[r][1]);
                    acc[r][0] = fma2(c0, w.y, acc[r][0]);
                    acc[r][1] = fma2(c1, w.y, acc[r][1]);
                }
                h0 = n0v; h1 = n1v;
            }
        }

        if (kg >= 4) {
#pragma unroll
            for (int r = 0; r < 9; r++) {
                RED(r, 0, kg - 4, lane) = acc[r][0];
                RED(r, 1, kg - 4, lane) = acc[r][1];
            }
        }
        __syncthreads();
        if (kg < 4) {
#pragma unroll
            for (int r = 0; r < 9; r++) {
                RED(r, 0, kg, lane) = add2(RED(r, 0, kg, lane), acc[r][0]);
                RED(r, 1, kg, lane) = add2(RED(r, 1, kg, lane), acc[r][1]);
            }
        }
        __syncthreads();

        if (gate) {
            unsigned long long s[3];
#pragma unroll
            for (int g = 0; g < 3; g++) {
                int r = gp * 3 + g;
                unsigned long long v = RED(r, gc, 0, glan);
                v = add2(v, RED(r, gc, 1, glan));
                v = add2(v, RED(r, gc, 2, glan));
                v = add2(v, RED(r, gc, 3, glan));
                s[g] = v;
            }
            float* houtT = g_temporalT + (size_t)t * H * B + gbb;
#pragma unroll
            for (int c = 0; c < 2; c++) {
                float gh_r = ((c == 0) ? lo32(s[0]) : hi32(s[0])) + gbias[c][0];
                float gh_z = ((c == 0) ? lo32(s[1]) : hi32(s[1])) + gbias[c][1];
                float gh_n = ((c == 0) ? lo32(s[2]) : hi32(s[2])) + gbias[c][2];
                float r = fsigmoid(gi[c][0] + gh_r);
                float z = fsigmoid(gi[c][1] + gh_z);
                float n = ftanh(gi[c][2] + r * gh_n);
                houtT[(size_t)(gja + c) * B] = (1.f - z) * n + z * hp[c];
            }
        }

        if (t < T - 1) half_barrier(bh, cb, (unsigned)(t + 1));
    }
}

// ---------------- Kernel 3a: heads GEMM -> logits ----------------
#define BK 16
__global__ __launch_bounds__(256) void heads_gemm(const float* __restrict__ Wc,
                                                  const float* __restrict__ bc,
                                                  const float* __restrict__ Wf,
                                                  const float* __restrict__ bf) {
    __shared__ float As[BK][128];
    __shared__ float Ws[BK][32];
    const int t  = blockIdx.x >> 1;
    const int b0 = (blockIdx.x & 1) * 128;
    const int tid = threadIdx.x;
    const int tx = tid % 8;
    const int ty = tid / 8;

    float acc[4][4];
#pragma unroll
    for (int i = 0; i < 4; i++)
#pragma unroll
        for (int j = 0; j < 4; j++) acc[i][j] = 0.f;

    const float* hT = g_temporalT + (size_t)t * H * B;

    for (int kt = 0; kt < H; kt += BK) {
#pragma unroll
        for (int l = 0; l < 2; l++) {
            int idx = tid + l * 256;
            int krow = idx >> 5;
            int bq = idx & 31;
            *(float4*)&As[krow][bq * 4] =
                *(const float4*)(hT + (size_t)(kt + krow) * B + b0 + bq * 4);
        }
        if (tid < 128) {
            int n = tid >> 2;
            int kq = tid & 3;
            float4 v = make_float4(0.f, 0.f, 0.f, 0.f);
            if (n < 2)       v = *(const float4*)(Wc + (size_t)n * H + kt + kq * 4);
            else if (n < 31) v = *(const float4*)(Wf + (size_t)(n - 2) * H + kt + kq * 4);
            Ws[kq * 4 + 0][n] = v.x;
            Ws[kq * 4 + 1][n] = v.y;
            Ws[kq * 4 + 2][n] = v.z;
            Ws[kq * 4 + 3][n] = v.w;
        }
        __syncthreads();
#pragma unroll
        for (int k = 0; k < BK; k++) {
            float a[4], w[4];
            *(float4*)a = *(const float4*)&As[k][ty * 4];
            *(float4*)w = *(const float4*)&Ws[k][tx * 4];
#pragma unroll
            for (int i = 0; i < 4; i++)
#pragma unroll
                for (int j = 0; j < 4; j++)
                    acc[i][j] = fmaf(a[i], w[j], acc[i][j]);
        }
        __syncthreads();
    }

#pragma unroll
    for (int i = 0; i < 4; i++) {
        int b = b0 + ty * 4 + i;
        float4 v;
        float* vp = (float*)&v;
#pragma unroll
        for (int j = 0; j < 4; j++) {
            int n = tx * 4 + j;
            float bias = (n < 2) ? bc[n] : ((n < 31) ? bf[n - 2] : 0.f);
            vp[j] = acc[i][j] + bias;
        }
        *(float4*)&g_logits[((size_t)t * B + b) * 32 + tx * 4] = v;
    }
}

// ---------------- Kernel 3b: activations ----------------
__global__ __launch_bounds__(256) void act_kernel(float* __restrict__ out) {
    int idx = blockIdx.x * blockDim.x + threadIdx.x;
    if (idx >= B * T) return;
    int t = idx >> 8;
    int b = idx & 255;
    const float* lg = g_logits + (size_t)idx * 32;
    float logit[32];
#pragma unroll
    for (int q = 0; q < 8; q++)
        *(float4*)&logit[q * 4] = *(const float4*)&lg[q * 4];

    float l0 = logit[0], l1 = logit[1];
    float m = fmaxf(l0, l1);
    float e0 = __expf(l0 - m), e1 = __expf(l1 - m);
    float inv = 1.f / (e0 + e1);
    size_t oidx = (size_t)b * T + t;
    g_scores[oidx * 2 + 0] = e0 * inv;
    g_scores[oidx * 2 + 1] = e1 * inv;

    float* fine = out + OUT_FINE_OFF + oidx * NC;
#pragma unroll
    for (int i = 0; i < NC; i++) fine[i] = fsigmoid(logit[2 + i]);
}

// ---------------- Kernel 4: NMS + decisions ----------------
__global__ void nms_kernel(float* __restrict__ out) {
    int idx = blockIdx.x * blockDim.x + threadIdx.x;
    if (idx >= B * T) return;
    int b = idx / T;
    int t = idx % T;
    const float* sb = g_scores + (size_t)b * T * 2;
    float s0 = sb[t * 2 + 0];
    float s1 = sb[t * 2 + 1];
    float wmin = INFINITY;
#pragma unroll
    for (int k = -2; k <= 2; k++) {
        int tt = t + k;
        if (tt >= 0 && tt < T) wmin = fminf(wmin, sb[tt * 2]);
    }
    bool keep = (s0 == wmin);
    float o0 = keep ? s0 : 0.f;
    float o1 = keep ? s1 : 0.f;
    out[idx] = (o1 > o0) ? 1.0f : 0.0f;
    out[OUT_NMS_OFF + (size_t)idx * 2 + 0] = o0;
    out[OUT_NMS_OFF + (size_t)idx * 2 + 1] = o1;
}

// ---------------- launch ----------------
extern "C" void kernel_launch(void* const* d_in, const int* in_sizes, int n_in,
                              void* d_out, int out_size) {
    const float* feat = (const float*)d_in[0];
    const float* Wi  = (const float*)d_in[2];
    const float* Wh  = (const float*)d_in[3];
    const float* bi  = (const float*)d_in[4];
    const float* bhb = (const float*)d_in[5];
    const float* Wc  = (const float*)d_in[6];
    const float* bc  = (const float*)d_in[7];
    const float* Wf  = (const float*)d_in[8];
    const float* bf  = (const float*)d_in[9];
    float* out = (float*)d_out;

    cudaFuncSetAttribute(xproj_mma, cudaFuncAttributeMaxDynamicSharedMemorySize, XMM_SMEM);

    // order: xproj_mma lands in the ncu-profiled slot (4th launch)
    reset_arrive_kernel<<<1, 256>>>();                          // 1
    reset_release_kernel<<<1, 64>>>();                          // 2
    split_kernel<<<1024, 256>>>(feat, Wi);                      // 3
    dim3 g1(96, 12);                                            // (48 t-pairs x 2 b-halves) x 12 g
    xproj_mma<<<g1, 256, XMM_SMEM>>>(bi);                       // 4 <- profiled
    gru_persistent<<<GRU_GRID, GRU_THR>>>(Wh, bhb);             // 5
    heads_gemm<<<T * 2, 256>>>(Wc, bc, Wf, bf);                 // 6
    act_kernel<<<(B * T + 255) / 256, 256>>>(out);              // 7
    nms_kernel<<<(B * T + 255) / 256, 256>>>(out);              // 8
}